// round 7
// baseline (speedup 1.0000x reference)
#include <cuda_runtime.h>
#include <math.h>

#define NN   20000
#define NE   320000
#define FIN  6
#define HID  128
#define NCLS 21
#define NL   4
#define NG   16
#define EPSV 1e-5f
#define NPB  4          // nodes per block in edge kernel
#define BM   128        // GEMM tile: nodes per block
#define NBLK ((NN + BM - 1) / BM)
#define RBF_BLKS (NE / 256)          // 1250
#define EMB_BLKS (NN / 2)            // 10000 (2 nodes per 256-thr block)

// ---------------- scratch (device globals; no runtime allocation) ----------
__device__ float g_e[NE * NG];         // RBF expansion, CSR edge order [E,16]
__device__ float g_h[NN * HID];        // node features
__device__ float g_pi[NN * HID * 2];   // interleaved (f,s) dst-path projection
__device__ float g_pj[NN * HID * 2];   // interleaved (f,s) src-path projection
__device__ float g_agg[NN * HID];      // aggregated messages
__device__ float g_cstat[2 * HID];     // BN column sum / sumsq (self-restoring)
__device__ float g_bnsc[HID];
__device__ float g_bnsh[HID];
__device__ int   g_rowptr[NN + 1];     // CSR row pointers (by dst)
__device__ int   g_cursor[NN];         // degree counter / scatter cursor (self-restoring)
__device__ int   g_csrc[NE];           // src node per CSR slot
__device__ int   g_ceid[NE];           // original edge id per CSR slot

// ---------------- CSR build ------------------------------------------------
__global__ void k_hist(const int* __restrict__ eidx) {
    int e = blockIdx.x * blockDim.x + threadIdx.x;
    if (e < NE) atomicAdd(&g_cursor[eidx[NE + e]], 1);
}

__global__ void k_scan() {   // single block, 1024 threads
    __shared__ int sp_[1024];
    int t = threadIdx.x;
    const int CH = 20;
    int base = t * CH;
    int lim = min(base + CH, NN);
    int sum = 0;
    for (int i = base; i < lim; i++) sum += g_cursor[i];
    sp_[t] = sum;
    __syncthreads();
    for (int off = 1; off < 1024; off <<= 1) {
        int v = (t >= off) ? sp_[t - off] : 0;
        __syncthreads();
        sp_[t] += v;
        __syncthreads();
    }
    int run = (t > 0) ? sp_[t - 1] : 0;
    for (int i = base; i < lim; i++) {
        int d = g_cursor[i];
        g_rowptr[i] = run;
        g_cursor[i] = run;   // reset cursor to row start for scatter
        run += d;
    }
    if (t == 0) g_rowptr[NN] = NE;
}

__global__ void k_scatter(const int* __restrict__ eidx) {
    int e = blockIdx.x * blockDim.x + threadIdx.x;
    if (e >= NE) return;
    int src = eidx[e];
    int dst = eidx[NE + e];
    int pos = atomicAdd(&g_cursor[dst], 1);
    g_csrc[pos] = src;
    g_ceid[pos] = e;
}

// ---------------- fused: RBF (CSR order) + node embedding + cursor reset ---
__global__ __launch_bounds__(256) void k_rbf_embed(const float* __restrict__ dist,
                                                   const float* __restrict__ x,
                                                   const float* __restrict__ Wn,
                                                   const float* __restrict__ bn) {
    int b = blockIdx.x;
    if (b < RBF_BLKS) {
        int i = b * 256 + threadIdx.x;        // CSR edge slot
        if (i < NN) g_cursor[i] = 0;          // restore invariant for next replay
        float d = dist[g_ceid[i]];
        const float coeff = -1.7578125f;      // -0.5 / (8/15)^2
        const float step  = 8.0f / 15.0f;
        float4* p = reinterpret_cast<float4*>(g_e + (size_t)i * NG);
#pragma unroll
        for (int j = 0; j < 4; j++) {
            float4 v;
            float dd;
            dd = d - (4 * j + 0) * step; v.x = __expf(coeff * dd * dd);
            dd = d - (4 * j + 1) * step; v.y = __expf(coeff * dd * dd);
            dd = d - (4 * j + 2) * step; v.z = __expf(coeff * dd * dd);
            dd = d - (4 * j + 3) * step; v.w = __expf(coeff * dd * dd);
            p[j] = v;
        }
    } else {
        int nb = b - RBF_BLKS;
        int n = nb * 2 + (threadIdx.x >> 7);
        int c = threadIdx.x & 127;
        const float* xr = x + (size_t)n * FIN;
        float a = bn[c];
#pragma unroll
        for (int k = 0; k < FIN; k++) a = fmaf(__ldg(&xr[k]), Wn[k * HID + c], a);
        g_h[(size_t)n * HID + c] = a;
    }
}

// ---------------- tiled GEMM projection ------------------------------------
__global__ __launch_bounds__(256) void k_proj(const float* __restrict__ Wf,
                                              const float* __restrict__ Ws,
                                              int l) {
    __shared__ float shH[BM][HID];     // [m][k]
    __shared__ float shW[HID][HID];    // [k][n]
    int tid = threadIdx.x;
    int fs   = blockIdx.y & 1;         // 0 -> Wf, 1 -> Ws
    int path = blockIdx.y >> 1;        // 0 -> i-path, 1 -> j-path
    const float* Wl = (fs == 0 ? Wf : Ws) + (size_t)l * 272 * HID + (size_t)path * HID * HID;
    float* outp = (path == 0) ? g_pi : g_pj;
    int m0 = blockIdx.x * BM;

#pragma unroll
    for (int i = 0; i < 16; i++) {
        int idx = tid + i * 256;           // float4 index
        int r = idx >> 5, q = idx & 31;
        int node = min(m0 + r, NN - 1);
        reinterpret_cast<float4*>(&shH[r][0])[q] =
            reinterpret_cast<const float4*>(g_h + (size_t)node * HID)[q];
        reinterpret_cast<float4*>(&shW[r][0])[q] =
            reinterpret_cast<const float4*>(Wl + (size_t)r * HID)[q];
    }
    __syncthreads();

    int nt = (tid & 15) * 8;   // col base
    int mt = (tid >> 4) * 8;   // local row base
    float acc[8][8];
#pragma unroll
    for (int i = 0; i < 8; i++)
#pragma unroll
        for (int j = 0; j < 8; j++) acc[i][j] = 0.f;

#pragma unroll 8
    for (int k = 0; k < HID; k++) {
        float b[8];
        float4 b0 = *reinterpret_cast<float4*>(&shW[k][nt]);
        float4 b1 = *reinterpret_cast<float4*>(&shW[k][nt + 4]);
        b[0] = b0.x; b[1] = b0.y; b[2] = b0.z; b[3] = b0.w;
        b[4] = b1.x; b[5] = b1.y; b[6] = b1.z; b[7] = b1.w;
        float a[8];
#pragma unroll
        for (int i = 0; i < 8; i++) a[i] = shH[mt + i][k];
#pragma unroll
        for (int i = 0; i < 8; i++)
#pragma unroll
            for (int j = 0; j < 8; j++)
                acc[i][j] = fmaf(a[i], b[j], acc[i][j]);
    }

#pragma unroll
    for (int i = 0; i < 8; i++) {
        int node = m0 + mt + i;
        if (node >= NN) break;
        float* orow = outp + (size_t)node * (2 * HID) + fs;
#pragma unroll
        for (int j = 0; j < 8; j++) orow[2 * (nt + j)] = acc[i][j];
    }
}

// ---------------- per-edge message (inlined; se4 points into smem) ---------
__device__ __forceinline__ float edge_msg(float zfb, float zsb, float2 pj,
                                          const float4* se4,
                                          const float wfe[NG], const float wse[NG]) {
    float4 ea = se4[0], eb = se4[1], ec = se4[2], ed = se4[3];
    float zf = zfb + pj.x;
    float zs = zsb + pj.y;
    float f0 = fmaf(ea.x, wfe[0],  fmaf(ea.y, wfe[1],  fmaf(ea.z, wfe[2],  ea.w * wfe[3])));
    float f1 = fmaf(eb.x, wfe[4],  fmaf(eb.y, wfe[5],  fmaf(eb.z, wfe[6],  eb.w * wfe[7])));
    float f2 = fmaf(ec.x, wfe[8],  fmaf(ec.y, wfe[9],  fmaf(ec.z, wfe[10], ec.w * wfe[11])));
    float f3 = fmaf(ed.x, wfe[12], fmaf(ed.y, wfe[13], fmaf(ed.z, wfe[14], ed.w * wfe[15])));
    float s0 = fmaf(ea.x, wse[0],  fmaf(ea.y, wse[1],  fmaf(ea.z, wse[2],  ea.w * wse[3])));
    float s1 = fmaf(eb.x, wse[4],  fmaf(eb.y, wse[5],  fmaf(eb.z, wse[6],  eb.w * wse[7])));
    float s2 = fmaf(ec.x, wse[8],  fmaf(ec.y, wse[9],  fmaf(ec.z, wse[10], ec.w * wse[11])));
    float s3 = fmaf(ed.x, wse[12], fmaf(ed.y, wse[13], fmaf(ed.z, wse[14], ed.w * wse[15])));
    zf += (f0 + f1) + (f2 + f3);
    zs += (s0 + s1) + (s2 + s3);
    float fg = __fdividef(1.0f, 1.0f + __expf(-zf));
    float sp = fmaxf(zs, 0.0f) + __logf(1.0f + __expf(-fabsf(zs)));
    return fg * sp;
}

// ---------------- CSR edge aggregation, MLP-4 prefetch + fused BN stats ----
__global__ __launch_bounds__(HID) void k_edge(const float* __restrict__ Wf,
                                              const float* __restrict__ bf,
                                              const float* __restrict__ Ws,
                                              const float* __restrict__ bs,
                                              int l) {
    __shared__ float4 se[512];     // up to 128 edges * 16 floats of RBF
    __shared__ int ssrc[128];
    int c = threadIdx.x;
    const float* Wfe = Wf + (size_t)l * 272 * HID + 256 * HID;
    const float* Wse = Ws + (size_t)l * 272 * HID + 256 * HID;
    float wfe[NG], wse[NG];
#pragma unroll
    for (int k = 0; k < NG; k++) {
        wfe[k] = __ldg(&Wfe[k * HID + c]);
        wse[k] = __ldg(&Wse[k * HID + c]);
    }
    float bfc = __ldg(&bf[l * HID + c]);
    float bsc = __ldg(&bs[l * HID + c]);
    for (int nn = 0; nn < NPB; nn++) {
        int n = blockIdx.x * NPB + nn;
        float2 pi = *reinterpret_cast<const float2*>(g_pi + (size_t)n * (2 * HID) + 2 * c);
        float zfb = pi.x + bfc;
        float zsb = pi.y + bsc;
        int start = g_rowptr[n], end = g_rowptr[n + 1];
        float a0 = 0.f, a1 = 0.f, a2 = 0.f, a3 = 0.f;
        for (int j0 = start; j0 < end; j0 += 128) {
            int cnt = min(128, end - j0);
            if (c < cnt) ssrc[c] = g_csrc[j0 + c];
            const float4* ge4 = reinterpret_cast<const float4*>(g_e) + (size_t)j0 * 4;
            for (int t = c; t < cnt * 4; t += HID) se[t] = ge4[t];
            __syncthreads();
            int i = 0;
            for (; i + 4 <= cnt; i += 4) {
                // batch the 4 random gathers first (MLP = 4)
                int s0i = ssrc[i], s1i = ssrc[i + 1], s2i = ssrc[i + 2], s3i = ssrc[i + 3];
                float2 pj0 = *reinterpret_cast<const float2*>(g_pj + (size_t)s0i * (2 * HID) + 2 * c);
                float2 pj1 = *reinterpret_cast<const float2*>(g_pj + (size_t)s1i * (2 * HID) + 2 * c);
                float2 pj2 = *reinterpret_cast<const float2*>(g_pj + (size_t)s2i * (2 * HID) + 2 * c);
                float2 pj3 = *reinterpret_cast<const float2*>(g_pj + (size_t)s3i * (2 * HID) + 2 * c);
                a0 += edge_msg(zfb, zsb, pj0, &se[(i + 0) * 4], wfe, wse);
                a1 += edge_msg(zfb, zsb, pj1, &se[(i + 1) * 4], wfe, wse);
                a2 += edge_msg(zfb, zsb, pj2, &se[(i + 2) * 4], wfe, wse);
                a3 += edge_msg(zfb, zsb, pj3, &se[(i + 3) * 4], wfe, wse);
            }
            for (; i < cnt; i++) {
                int s = ssrc[i];
                float2 pj = *reinterpret_cast<const float2*>(g_pj + (size_t)s * (2 * HID) + 2 * c);
                a0 += edge_msg(zfb, zsb, pj, &se[i * 4], wfe, wse);
            }
            __syncthreads();
        }
        float acc = (a0 + a1) + (a2 + a3);
        g_agg[(size_t)n * HID + c] = acc;
        atomicAdd(&g_cstat[c], acc);              // REDG, fire-and-forget
        atomicAdd(&g_cstat[HID + c], acc * acc);
    }
}

// ---------------- BN finalize (also zeros cstat for next layer/replay) -----
__global__ void k_bnfin(const float* __restrict__ bn_g,
                        const float* __restrict__ bn_b, int l) {
    int c = threadIdx.x;
    float sum = g_cstat[c], sq = g_cstat[HID + c];
    g_cstat[c] = 0.f;
    g_cstat[HID + c] = 0.f;
    float mu = sum * (1.0f / NN);
    float var = sq * (1.0f / NN) - mu * mu;
    float sc = bn_g[l * HID + c] * rsqrtf(var + EPSV);
    g_bnsc[c] = sc;
    g_bnsh[c] = fmaf(-mu, sc, bn_b[l * HID + c]);
}

// ---------------- fused BN-apply + residual + LayerNorm + ReLU + residual --
__global__ __launch_bounds__(HID) void k_update(const float* __restrict__ ln_g,
                                                const float* __restrict__ ln_b,
                                                int l) {
    int n = blockIdx.x, c = threadIdx.x;
    float h = g_h[(size_t)n * HID + c];
    float v = fmaf(g_agg[(size_t)n * HID + c], g_bnsc[c], g_bnsh[c]) + h;
    float s = v, q = v * v;
#pragma unroll
    for (int o = 16; o > 0; o >>= 1) {
        s += __shfl_xor_sync(0xffffffffu, s, o);
        q += __shfl_xor_sync(0xffffffffu, q, o);
    }
    __shared__ float ss[4], sq[4], smv[2];
    int w = c >> 5;
    if ((c & 31) == 0) { ss[w] = s; sq[w] = q; }
    __syncthreads();
    if (c == 0) {
        float ts = ss[0] + ss[1] + ss[2] + ss[3];
        float tq = sq[0] + sq[1] + sq[2] + sq[3];
        float m = ts * (1.0f / HID);
        float var = tq * (1.0f / HID) - m * m;
        smv[0] = m; smv[1] = rsqrtf(var + EPSV);
    }
    __syncthreads();
    float hn = fmaf((v - smv[0]) * smv[1], ln_g[l * HID + c], ln_b[l * HID + c]);
    g_h[(size_t)n * HID + c] = fmaxf(hn, 0.0f) + h;
}

// ---------------- final LayerNorm + FC -------------------------------------
__global__ __launch_bounds__(HID) void k_out(const float* __restrict__ lng,
                                             const float* __restrict__ lnb,
                                             const float* __restrict__ Wfc,
                                             const float* __restrict__ bfc,
                                             float* __restrict__ out) {
    int n = blockIdx.x, c = threadIdx.x;
    float h = g_h[(size_t)n * HID + c];
    float s = h, q = h * h;
#pragma unroll
    for (int o = 16; o > 0; o >>= 1) {
        s += __shfl_xor_sync(0xffffffffu, s, o);
        q += __shfl_xor_sync(0xffffffffu, q, o);
    }
    __shared__ float ss[4], sq[4], smv[2];
    __shared__ float sh[HID];
    int w = c >> 5;
    if ((c & 31) == 0) { ss[w] = s; sq[w] = q; }
    __syncthreads();
    if (c == 0) {
        float ts = ss[0] + ss[1] + ss[2] + ss[3];
        float tq = sq[0] + sq[1] + sq[2] + sq[3];
        float m = ts * (1.0f / HID);
        float var = tq * (1.0f / HID) - m * m;
        smv[0] = m; smv[1] = rsqrtf(var + EPSV);
    }
    __syncthreads();
    sh[c] = fmaf((h - smv[0]) * smv[1], lng[c], lnb[c]);
    __syncthreads();
    if (c < NCLS) {
        float a = bfc[c];
#pragma unroll 16
        for (int k = 0; k < HID; k++) a = fmaf(sh[k], Wfc[k * NCLS + c], a);
        out[(size_t)n * NCLS + c] = a;
    }
}

// ---------------- launch ----------------------------------------------------
// g_cursor / g_cstat invariants: zero at module load; k_rbf_embed re-zeros
// cursor after k_scatter consumes it; k_bnfin re-zeros cstat after reading.
// So each kernel_launch call leaves both zeroed -> deterministic replays,
// no memsets needed. Launch index 5 == k_edge(l=0) for ncu -s 5 -c 1.
extern "C" void kernel_launch(void* const* d_in, const int* in_sizes, int n_in,
                              void* d_out, int out_size) {
    const float* x    = (const float*)d_in[0];
    const int*   eidx = (const int*)  d_in[1];
    const float* dist = (const float*)d_in[2];
    const float* Wn   = (const float*)d_in[3];
    const float* bn   = (const float*)d_in[4];
    const float* Wf   = (const float*)d_in[5];
    const float* bf   = (const float*)d_in[6];
    const float* Ws   = (const float*)d_in[7];
    const float* bs   = (const float*)d_in[8];
    const float* bng  = (const float*)d_in[9];
    const float* bnb  = (const float*)d_in[10];
    const float* lng  = (const float*)d_in[11];
    const float* lnb  = (const float*)d_in[12];
    const float* log_ = (const float*)d_in[13];
    const float* lob  = (const float*)d_in[14];
    const float* Wfc  = (const float*)d_in[15];
    const float* bfc  = (const float*)d_in[16];
    float* out = (float*)d_out;

    k_hist<<<(NE + 255) / 256, 256>>>(eidx);                      // 0
    k_scan<<<1, 1024>>>();                                        // 1
    k_scatter<<<(NE + 255) / 256, 256>>>(eidx);                   // 2
    k_rbf_embed<<<RBF_BLKS + EMB_BLKS, 256>>>(dist, x, Wn, bn);   // 3

    for (int l = 0; l < NL; l++) {
        k_proj<<<dim3(NBLK, 4), 256>>>(Wf, Ws, l);                // 4 (l=0)
        k_edge<<<NN / NPB, HID>>>(Wf, bf, Ws, bs, l);             // 5 (l=0) <- profiled
        k_bnfin<<<1, HID>>>(bng, bnb, l);
        k_update<<<NN, HID>>>(lng, lnb, l);
    }
    k_out<<<NN, HID>>>(log_, lob, Wfc, bfc, out);
}